// round 7
// baseline (speedup 1.0000x reference)
#include <cuda_runtime.h>
#include <cuda_bf16.h>
#include <cstdint>

// Problem constants
#define T_STEPS 512
#define BATCH   64
#define HID     512
#define GATES   1536   // 3*HID
#define NLAYERS 2

// Scratch (device globals; no allocation)
__device__ float g_gates[(size_t)T_STEPS * BATCH * GATES];   // input gates
__device__ float g_buf1[(size_t)T_STEPS * BATCH * HID];      // layer-1 output
__device__ float g_wfrag[(size_t)192 * 64 * 32 * 2];         // frag-ordered W_ih

// Per-batch-group software barriers (4 groups x 32 CTAs)
struct alignas(128) BarSt { unsigned arrive; unsigned gen; unsigned pad[30]; };
__device__ BarSt g_bars[4];

__device__ __forceinline__ uint32_t f32_to_tf32(float f) {
    uint32_t u;
    asm("cvt.rna.tf32.f32 %0, %1;" : "=r"(u) : "f"(f));
    return u;
}

#define MMA_TF32(acc, a0, a1, a2, a3, b0, b1)                                  \
    asm volatile(                                                              \
        "mma.sync.aligned.m16n8k8.row.col.f32.tf32.tf32.f32 "                  \
        "{%0,%1,%2,%3}, {%4,%5,%6,%7}, {%8,%9}, {%0,%1,%2,%3};\n"              \
        : "+f"((acc)[0]), "+f"((acc)[1]), "+f"((acc)[2]), "+f"((acc)[3])       \
        : "r"(a0), "r"(a1), "r"(a2), "r"(a3), "r"(b0), "r"(b1))

__device__ __forceinline__ void cp_async16(uint32_t dst, const void* src) {
    asm volatile("cp.async.cg.shared.global [%0], [%1], 16;" :: "r"(dst), "l"(src));
}

__device__ __forceinline__ unsigned ld_acq_gpu(unsigned* p) {
    unsigned v;
    asm volatile("ld.acquire.gpu.global.u32 %0, [%1];" : "=r"(v) : "l"(p) : "memory");
    return v;
}
__device__ __forceinline__ unsigned atom_add_rel_gpu(unsigned* p) {
    unsigned old;
    asm volatile("atom.add.release.gpu.global.u32 %0, [%1], 1;"
                 : "=r"(old) : "l"(p) : "memory");
    return old;
}

// ---------------------------------------------------------------------------
// Pre-convert W (N=1536, K=512 row-major fp32) into MMA B-fragment order.
// ---------------------------------------------------------------------------
__global__ __launch_bounds__(256) void conv_wfrag(
    const float* __restrict__ W, uint32_t* __restrict__ F)
{
    int idx = blockIdx.x * 256 + threadIdx.x;
    int r    = idx & 1;
    int lane = (idx >> 1) & 31;
    int k8   = (idx >> 6) & 63;
    int nt   = idx >> 12;
    int n = nt * 8 + (lane >> 2);
    int k = k8 * 8 + (lane & 3) + 4 * r;
    F[idx] = f32_to_tf32(W[(size_t)n * HID + k]);
}

// ---------------------------------------------------------------------------
// GEMM v3:  C[m,n] = sum_k A[m,k] * W[n,k] + bias[n]
// CTA tile 128(M) x 128(N); 8 warps = 2(m) x 4(n); warp tile 64x32
// (4 m-tiles x 4 n-tiles = 16 MMAs per k8 step -> half the per-MMA overhead).
// A staged via cp.async double buffer; B from frag-ordered global (L2 reuse).
// ---------------------------------------------------------------------------
#define AP 36   // A smem pitch (floats)

__global__ __launch_bounds__(256) void gemm_tf32_v3(
    const float* __restrict__ A, const uint32_t* __restrict__ Wf,
    const float* __restrict__ bias, float* __restrict__ C,
    int M, int N, int K)
{
    __shared__ float As[2][128][AP];   // 2 x 128 x 36 x 4B = 36864 B

    const int bm  = blockIdx.y * 128;
    const int bnt = blockIdx.x * 16;      // base n-tile (128 cols / 8)
    const int tid = threadIdx.x;
    const int wid = tid >> 5;
    const int lane = tid & 31;
    const int wm = wid & 1;               // m half (64 rows)
    const int wn = wid >> 1;              // n quarter (32 cols)
    const int frow = lane >> 2;
    const int fk = lane & 3;

    float acc[4][4][4];
#pragma unroll
    for (int i = 0; i < 4; i++)
#pragma unroll
        for (int j = 0; j < 4; j++)
#pragma unroll
            for (int e = 0; e < 4; e++) acc[i][j][e] = 0.0f;

    // loader mapping: 1024 float4 per stage, 4 per thread
    const int lrow = tid >> 1;            // 0..127
    const int lcol = (tid & 1) * 4;       // float4 index 0 or 4

    auto issue_stage = [&](int k0, int buf) {
#pragma unroll
        for (int it = 0; it < 2; it++) {
            int c4 = lcol + it;                    // 2 of the 8 col4 slots
            uint32_t dst = (uint32_t)__cvta_generic_to_shared(&As[buf][lrow][c4 * 4]);
            cp_async16(dst, A + (size_t)(bm + lrow) * K + k0 + c4 * 4);
        }
#pragma unroll
        for (int it = 0; it < 2; it++) {
            int c4 = lcol + 2 + it;
            uint32_t dst = (uint32_t)__cvta_generic_to_shared(&As[buf][lrow][c4 * 4]);
            cp_async16(dst, A + (size_t)(bm + lrow) * K + k0 + c4 * 4);
        }
        asm volatile("cp.async.commit_group;");
    };

    issue_stage(0, 0);
    int buf = 0;

    for (int k0 = 0; k0 < K; k0 += 32) {
        asm volatile("cp.async.wait_group 0;");
        __syncthreads();
        if (k0 + 32 < K) issue_stage(k0 + 32, buf ^ 1);

#pragma unroll
        for (int k8 = 0; k8 < 4; k8++) {
            const int kb = k8 * 8;
            const int k8g = (k0 >> 3) + k8;
            uint32_t b0[4], b1[4];
#pragma unroll
            for (int j = 0; j < 4; j++) {
                size_t nt = (size_t)(bnt + wn * 4 + j);
                const uint2 v = __ldg((const uint2*)(Wf + ((nt * 64 + k8g) * 32 + lane) * 2));
                b0[j] = v.x; b1[j] = v.y;
            }
            uint32_t a[4][4];
#pragma unroll
            for (int i = 0; i < 4; i++) {
                int r0 = wm * 64 + i * 16 + frow;
                a[i][0] = f32_to_tf32(As[buf][r0][kb + fk]);
                a[i][1] = f32_to_tf32(As[buf][r0 + 8][kb + fk]);
                a[i][2] = f32_to_tf32(As[buf][r0][kb + 4 + fk]);
                a[i][3] = f32_to_tf32(As[buf][r0 + 8][kb + 4 + fk]);
            }
#pragma unroll
            for (int i = 0; i < 4; i++)
#pragma unroll
                for (int j = 0; j < 4; j++)
                    MMA_TF32(acc[i][j], a[i][0], a[i][1], a[i][2], a[i][3],
                             b0[j], b1[j]);
        }
        buf ^= 1;
    }

    // epilogue: bias + store
#pragma unroll
    for (int i = 0; i < 4; i++) {
        int mrow = bm + wm * 64 + i * 16 + frow;
#pragma unroll
        for (int j = 0; j < 4; j++) {
            int ncol = (bnt + wn * 4 + j) * 8 + fk * 2;
            float c0 = bias[ncol], c1 = bias[ncol + 1];
            *(float2*)(C + (size_t)mrow * N + ncol) =
                make_float2(acc[i][j][0] + c0, acc[i][j][1] + c1);
            *(float2*)(C + (size_t)(mrow + 8) * N + ncol) =
                make_float2(acc[i][j][2] + c0, acc[i][j][3] + c1);
        }
    }
}

// ---------------------------------------------------------------------------
// Per-batch-group grid barrier (32 CTAs per group), acquire/release atomics.
// ---------------------------------------------------------------------------
__device__ __forceinline__ void group_barrier(int grp, unsigned nb)
{
    __syncthreads();
    if (threadIdx.x == 0) {
        unsigned gen0 = *(volatile unsigned*)&g_bars[grp].gen;
        unsigned prev = atom_add_rel_gpu(&g_bars[grp].arrive);
        if (prev == nb - 1) {
            *(volatile unsigned*)&g_bars[grp].arrive = 0;
            atom_add_rel_gpu(&g_bars[grp].gen);
        } else {
            while (ld_acq_gpu(&g_bars[grp].gen) == gen0) { }
        }
    }
    __syncthreads();
}

// ---------------------------------------------------------------------------
// Persistent recurrent kernel with tensor-core recurrent GEMM.
// grid = 128 CTAs = 32 j-tiles (16 hidden) x 4 b-groups (16 batch), 256 thr.
// W_hh fragments register-resident for all 512 steps.
// ---------------------------------------------------------------------------
#define HS_PITCH 520
#define PS_PITCH 50
#define REC_SMEM_FLOATS (16 * HS_PITCH + 8 * 16 * PS_PITCH)
#define REC_SMEM_BYTES (REC_SMEM_FLOATS * 4)

__global__ __launch_bounds__(256, 1) void gru_layer_mma(
    const float* __restrict__ gx_all,  // (T, B, 3H)
    const float* __restrict__ h0,      // (B, H)
    const float* __restrict__ Whh,     // (3H, H)
    const float* __restrict__ bhh,     // (3H)
    float* __restrict__ out)           // (T, B, H); out[t] doubles as h_t
{
    extern __shared__ float sm[];
    float* h_s = sm;                   // [16][HS_PITCH]
    float* Ps  = sm + 16 * HS_PITCH;   // [8][16][PS_PITCH]

    const int jt = blockIdx.x & 31;
    const int bt = blockIdx.x >> 5;
    const int j0 = jt * 16;
    const int b0 = bt * 16;
    const int tid = threadIdx.x;
    const int w = tid >> 5;
    const int lane = tid & 31;

    // W_hh fragments into registers (once). Warp w owns k8 in [w*8, w*8+8).
    uint32_t wb0[6][8], wb1[6][8];
    {
        const int colq = lane >> 2;
        const int kq = lane & 3;
#pragma unroll
        for (int tl = 0; tl < 6; tl++) {
            int g = tl >> 1;
            int col = j0 + (tl & 1) * 8 + colq;
            const float* wrow = Whh + (size_t)(g * HID + col) * HID;
#pragma unroll
            for (int kk = 0; kk < 8; kk++) {
                int k = (w * 8 + kk) * 8 + kq;
                wb0[tl][kk] = f32_to_tf32(wrow[k]);
                wb1[tl][kk] = f32_to_tf32(wrow[k + 4]);
            }
        }
    }

    const int gb = tid >> 4;
    const int gj = tid & 15;
    const int bg_g = b0 + gb;
    const int jg_g = j0 + gj;
    const float br_ = bhh[jg_g];
    const float bz_ = bhh[HID + jg_g];
    const float bn_ = bhh[2 * HID + jg_g];

    const int frow = lane >> 2;
    const int fk = lane & 3;

    // prefetch t=0 input-side gates
    const float* gxp = gx_all + (size_t)bg_g * GATES;
    float xr = __ldg(gxp + jg_g);
    float xz = __ldg(gxp + HID + jg_g);
    float xn = __ldg(gxp + 2 * HID + jg_g);

    for (int t = 0; t < T_STEPS; t++) {
        const float* hprev = (t == 0) ? h0 : out + (size_t)(t - 1) * BATCH * HID;

        // stage h tile (16 x 512 fp32), coalesced
#pragma unroll
        for (int q = 0; q < 8; q++) {
            int f = q * 256 + tid;
            int rr = f >> 7;
            int c4 = f & 127;
            float4 v = *((const float4*)(hprev + (size_t)(b0 + rr) * HID) + c4);
            *(float4*)&h_s[rr * HS_PITCH + c4 * 4] = v;
        }
        __syncthreads();

        // MMA over this warp's k-slice: 8 k8-steps x 6 n-tiles
        float acc[6][4];
#pragma unroll
        for (int tl = 0; tl < 6; tl++) {
            acc[tl][0] = 0.f; acc[tl][1] = 0.f; acc[tl][2] = 0.f; acc[tl][3] = 0.f;
        }
#pragma unroll
        for (int kk = 0; kk < 8; kk++) {
            int kbase = (w * 8 + kk) * 8;
            uint32_t a0 = f32_to_tf32(h_s[frow * HS_PITCH + kbase + fk]);
            uint32_t a1 = f32_to_tf32(h_s[(frow + 8) * HS_PITCH + kbase + fk]);
            uint32_t a2 = f32_to_tf32(h_s[frow * HS_PITCH + kbase + 4 + fk]);
            uint32_t a3 = f32_to_tf32(h_s[(frow + 8) * HS_PITCH + kbase + 4 + fk]);
#pragma unroll
            for (int tl = 0; tl < 6; tl++)
                MMA_TF32(acc[tl], a0, a1, a2, a3, wb0[tl][kk], wb1[tl][kk]);
        }
        {
            int m = lane >> 2;
            int ncb = 2 * (lane & 3);
#pragma unroll
            for (int tl = 0; tl < 6; tl++) {
                *(float2*)&Ps[(w * 16 + m) * PS_PITCH + tl * 8 + ncb] =
                    make_float2(acc[tl][0], acc[tl][1]);
                *(float2*)&Ps[(w * 16 + m + 8) * PS_PITCH + tl * 8 + ncb] =
                    make_float2(acc[tl][2], acc[tl][3]);
            }
        }
        __syncthreads();

        // reduce 8 partials + gating
        float hr = 0.f, hz = 0.f, hn = 0.f;
#pragma unroll
        for (int ww = 0; ww < 8; ww++) {
            const float* p = &Ps[(ww * 16 + gb) * PS_PITCH];
            hr += p[gj];
            hz += p[16 + gj];
            hn += p[32 + gj];
        }
        float r = 1.0f / (1.0f + __expf(-(xr + hr + br_)));
        float z = 1.0f / (1.0f + __expf(-(xz + hz + bz_)));
        float n = tanhf(xn + r * (hn + bn_));

        float hpv = h_s[gb * HS_PITCH + jg_g];
        out[(size_t)t * BATCH * HID + (size_t)bg_g * HID + jg_g] =
            (1.0f - z) * n + z * hpv;

        // prefetch next step's input-side gates (hides L2 behind barrier wait)
        int tn = (t + 1 < T_STEPS) ? t + 1 : t;
        const float* gxn = gx_all + (size_t)tn * BATCH * GATES + (size_t)bg_g * GATES;
        xr = __ldg(gxn + jg_g);
        xz = __ldg(gxn + HID + jg_g);
        xn = __ldg(gxn + 2 * HID + jg_g);

        if (t != T_STEPS - 1)
            group_barrier(bt, 32);
    }
}

// ---------------------------------------------------------------------------
extern "C" void kernel_launch(void* const* d_in, const int* in_sizes, int n_in,
                              void* d_out, int out_size)
{
    const float* x    = (const float*)d_in[0];
    const float* h0   = (const float*)d_in[1];
    const float* w_ih = (const float*)d_in[2];
    const float* w_hh = (const float*)d_in[3];
    const float* b_ih = (const float*)d_in[4];
    const float* b_hh = (const float*)d_in[5];
    float* out_final  = (float*)d_out;

    float* gates; float* buf1; uint32_t* wfrag;
    cudaGetSymbolAddress((void**)&gates, g_gates);
    cudaGetSymbolAddress((void**)&buf1, g_buf1);
    cudaGetSymbolAddress((void**)&wfrag, g_wfrag);

    static int smem_configured = 0;
    if (!smem_configured) {
        cudaFuncSetAttribute(gru_layer_mma,
                             cudaFuncAttributeMaxDynamicSharedMemorySize, REC_SMEM_BYTES);
        smem_configured = 1;
    }

    const int M = T_STEPS * BATCH;
    const int K = HID;

    for (int l = 0; l < NLAYERS; l++) {
        const float* inp   = (l == 0) ? x : buf1;
        float*       out   = (l == NLAYERS - 1) ? out_final : buf1;
        const float* wih_l = w_ih + (size_t)l * GATES * HID;
        const float* whh_l = w_hh + (size_t)l * GATES * HID;
        const float* bih_l = b_ih + (size_t)l * GATES;
        const float* bhh_l = b_hh + (size_t)l * GATES;
        const float* h0_l  = h0 + (size_t)l * BATCH * HID;

        conv_wfrag<<<3072, 256>>>(wih_l, wfrag);

        dim3 ggrid(GATES / 128, M / 128);
        gemm_tf32_v3<<<ggrid, 256>>>(inp, wfrag, bih_l, gates, M, GATES, K);

        gru_layer_mma<<<128, 256, REC_SMEM_BYTES>>>(gates, h0_l, whh_l, bhh_l, out);
    }
}

// round 8
// speedup vs baseline: 1.1311x; 1.1311x over previous
#include <cuda_runtime.h>
#include <cuda_fp16.h>
#include <cstdint>

// Problem constants
#define T_STEPS 512
#define BATCH   64
#define HID     512
#define GATES   1536   // 3*HID
#define NLAYERS 2

// Scratch (device globals; no allocation)
__device__ float g_gates[(size_t)T_STEPS * BATCH * GATES];   // input gates
__device__ float g_buf1[(size_t)T_STEPS * BATCH * HID];      // layer-1 output
__device__ uint32_t g_wfrag[(size_t)192 * 32 * 32 * 2];      // frag-ordered fp16 W_ih

// Per-batch-group software barriers (4 groups x 32 CTAs)
struct alignas(128) BarSt { unsigned arrive; unsigned gen; unsigned pad[30]; };
__device__ BarSt g_bars[4];

__device__ __forceinline__ uint32_t pack_h2(float a, float b) {
    __half2 h = __floats2half2_rn(a, b);
    return *(uint32_t*)&h;
}

#define MMA_F16(acc, a0, a1, a2, a3, b0, b1)                                   \
    asm volatile(                                                              \
        "mma.sync.aligned.m16n8k16.row.col.f32.f16.f16.f32 "                   \
        "{%0,%1,%2,%3}, {%4,%5,%6,%7}, {%8,%9}, {%0,%1,%2,%3};\n"              \
        : "+f"((acc)[0]), "+f"((acc)[1]), "+f"((acc)[2]), "+f"((acc)[3])       \
        : "r"(a0), "r"(a1), "r"(a2), "r"(a3), "r"(b0), "r"(b1))

__device__ __forceinline__ unsigned ld_acq_gpu(unsigned* p) {
    unsigned v;
    asm volatile("ld.acquire.gpu.global.u32 %0, [%1];" : "=r"(v) : "l"(p) : "memory");
    return v;
}
__device__ __forceinline__ unsigned atom_add_rel_gpu(unsigned* p) {
    unsigned old;
    asm volatile("atom.add.release.gpu.global.u32 %0, [%1], 1;"
                 : "=r"(old) : "l"(p) : "memory");
    return old;
}

// ---------------------------------------------------------------------------
// Pre-convert W (1536 x 512 row-major fp32) into fp16 MMA B-fragment order:
// F[((nt*32 + k16)*32 + lane)*2 + r] packs W[nt*8 + lane/4,
//   k16*16 + (lane%4)*2 + 8r + {0,1}]
// ---------------------------------------------------------------------------
__global__ __launch_bounds__(256) void conv_wfrag_h(
    const float* __restrict__ W, uint32_t* __restrict__ F)
{
    int idx = blockIdx.x * 256 + threadIdx.x;   // 0 .. 393215
    int r    = idx & 1;
    int lane = (idx >> 1) & 31;
    int k16  = (idx >> 6) & 31;
    int nt   = idx >> 11;
    int n = nt * 8 + (lane >> 2);
    int k = k16 * 16 + (lane & 3) * 2 + r * 8;
    const float* p = W + (size_t)n * HID + k;
    F[idx] = pack_h2(p[0], p[1]);
}

// ---------------------------------------------------------------------------
// fp16 GEMM:  C[m,n] = sum_k A[m,k] * W[n,k] + bias[n]
// CTA tile 64(M) x 128(N); 8 warps = 2(m) x 4(n); warp tile 32x32.
// A pre-converted to fp16 in SMEM (uint32-pair layout, pitch 20 -> no
// bank conflicts); B streamed from frag-ordered global buffer.
// ---------------------------------------------------------------------------
#define APH 20   // A smem pitch in uint32 (16 data + 4 pad)

__global__ __launch_bounds__(256) void gemm_f16(
    const float* __restrict__ A, const uint32_t* __restrict__ Wf,
    const float* __restrict__ bias, float* __restrict__ C,
    int M, int N, int K)
{
    __shared__ uint32_t As[2][64][APH];   // 10 KB

    const int bm  = blockIdx.y * 64;
    const int bnt = blockIdx.x * 16;
    const int tid = threadIdx.x;
    const int wid = tid >> 5;
    const int lane = tid & 31;
    const int wm = wid & 1;
    const int wn = wid >> 1;
    const int frow = lane >> 2;
    const int fk = lane & 3;

    float acc[2][4][4];
#pragma unroll
    for (int i = 0; i < 2; i++)
#pragma unroll
        for (int j = 0; j < 4; j++)
#pragma unroll
            for (int e = 0; e < 4; e++) acc[i][j][e] = 0.0f;

    const int lm = tid >> 2;          // 0..63 (row)
    const int lq = tid & 3;           // float4 slot base (2 per thread)

    float4 pre[2];
    auto ldA = [&](int k0) {
#pragma unroll
        for (int it = 0; it < 2; it++) {
            int kq = lq * 2 + it;     // 0..7
            pre[it] = *(const float4*)(A + (size_t)(bm + lm) * K + k0 + kq * 4);
        }
    };
    auto stA = [&](int buf) {
#pragma unroll
        for (int it = 0; it < 2; it++) {
            int kq = lq * 2 + it;
            uint2 u = make_uint2(pack_h2(pre[it].x, pre[it].y),
                                 pack_h2(pre[it].z, pre[it].w));
            *(uint2*)&As[buf][lm][kq * 2] = u;
        }
    };

    ldA(0);
    stA(0);
    int buf = 0;

    for (int k0 = 0; k0 < K; k0 += 32) {
        __syncthreads();
        bool next = (k0 + 32 < K);
        if (next) ldA(k0 + 32);

#pragma unroll
        for (int sub = 0; sub < 2; sub++) {
            const int k16g = (k0 >> 4) + sub;
            uint32_t b0[4], b1[4];
#pragma unroll
            for (int j = 0; j < 4; j++) {
                size_t nt = (size_t)(bnt + wn * 4 + j);
                const uint2 v = __ldg((const uint2*)(Wf + ((nt * 32 + k16g) * 32 + lane) * 2));
                b0[j] = v.x; b1[j] = v.y;
            }
            uint32_t a[2][4];
#pragma unroll
            for (int i = 0; i < 2; i++) {
                int r0 = wm * 32 + i * 16 + frow;
                a[i][0] = As[buf][r0][sub * 8 + fk];
                a[i][1] = As[buf][r0 + 8][sub * 8 + fk];
                a[i][2] = As[buf][r0][sub * 8 + 4 + fk];
                a[i][3] = As[buf][r0 + 8][sub * 8 + 4 + fk];
            }
#pragma unroll
            for (int i = 0; i < 2; i++)
#pragma unroll
                for (int j = 0; j < 4; j++)
                    MMA_F16(acc[i][j], a[i][0], a[i][1], a[i][2], a[i][3],
                            b0[j], b1[j]);
        }
        if (next) stA(buf ^ 1);
        buf ^= 1;
    }

    // epilogue: bias + store
#pragma unroll
    for (int i = 0; i < 2; i++) {
        int mrow = bm + wm * 32 + i * 16 + frow;
#pragma unroll
        for (int j = 0; j < 4; j++) {
            int ncol = (bnt + wn * 4 + j) * 8 + fk * 2;
            float c0 = bias[ncol], c1 = bias[ncol + 1];
            *(float2*)(C + (size_t)mrow * N + ncol) =
                make_float2(acc[i][j][0] + c0, acc[i][j][1] + c1);
            *(float2*)(C + (size_t)(mrow + 8) * N + ncol) =
                make_float2(acc[i][j][2] + c0, acc[i][j][3] + c1);
        }
    }
}

// ---------------------------------------------------------------------------
// Per-batch-group grid barrier (32 CTAs per group), acquire/release atomics.
// ---------------------------------------------------------------------------
__device__ __forceinline__ void group_barrier(int grp, unsigned nb)
{
    __syncthreads();
    if (threadIdx.x == 0) {
        unsigned gen0 = *(volatile unsigned*)&g_bars[grp].gen;
        unsigned prev = atom_add_rel_gpu(&g_bars[grp].arrive);
        if (prev == nb - 1) {
            *(volatile unsigned*)&g_bars[grp].arrive = 0;
            atom_add_rel_gpu(&g_bars[grp].gen);
        } else {
            while (ld_acq_gpu(&g_bars[grp].gen) == gen0) { }
        }
    }
    __syncthreads();
}

// ---------------------------------------------------------------------------
// Persistent recurrent kernel, fp16 MMA (m16n8k16).
// grid = 128 CTAs = 32 j-tiles (16 hidden) x 4 b-groups (16 batch), 256 thr.
// W_hh fragments register-resident (48 regs); h staged as fp16 in SMEM.
// ---------------------------------------------------------------------------
#define HSH_PITCH 520          // halfs per row; (520/2) % 32 == 4 -> conflict-free
#define PS_PITCH 50
#define REC_SMEM_BYTES (16 * HSH_PITCH * 2 + 8 * 16 * PS_PITCH * 4)

__global__ __launch_bounds__(256, 1) void gru_layer_mma(
    const float* __restrict__ gx_all,  // (T, B, 3H)
    const float* __restrict__ h0,      // (B, H)
    const float* __restrict__ Whh,     // (3H, H)
    const float* __restrict__ bhh,     // (3H)
    float* __restrict__ out)           // (T, B, H); out[t] doubles as h_t
{
    extern __shared__ float sm[];
    __half* h_sh = (__half*)sm;                       // [16][HSH_PITCH]
    float* Ps = sm + (16 * HSH_PITCH * 2) / 4;        // [8][16][PS_PITCH]

    const int jt = blockIdx.x & 31;
    const int bt = blockIdx.x >> 5;
    const int j0 = jt * 16;
    const int b0 = bt * 16;
    const int tid = threadIdx.x;
    const int w = tid >> 5;
    const int lane = tid & 31;

    // W_hh fp16 fragments into registers (once). Warp w owns k16-steps
    // [w*4, w*4+4). B-frag: col = lane>>2, k-pair base = (lane&3)*2.
    uint32_t wb0[6][4], wb1[6][4];
    {
        const int colq = lane >> 2;
        const int kq2 = (lane & 3) * 2;
#pragma unroll
        for (int tl = 0; tl < 6; tl++) {
            int g = tl >> 1;
            int col = j0 + (tl & 1) * 8 + colq;
            const float* wrow = Whh + (size_t)(g * HID + col) * HID;
#pragma unroll
            for (int kk = 0; kk < 4; kk++) {
                int ks = (w * 4 + kk) * 16 + kq2;
                wb0[tl][kk] = pack_h2(wrow[ks], wrow[ks + 1]);
                wb1[tl][kk] = pack_h2(wrow[ks + 8], wrow[ks + 9]);
            }
        }
    }

    const int gb = tid >> 4;
    const int gj = tid & 15;
    const int bg_g = b0 + gb;
    const int jg_g = j0 + gj;
    const float br_ = bhh[jg_g];
    const float bz_ = bhh[HID + jg_g];
    const float bn_ = bhh[2 * HID + jg_g];

    const int frow = lane >> 2;
    const int fk = lane & 3;

    // prefetch t=0 input-side gates
    const float* gxp = gx_all + (size_t)bg_g * GATES;
    float xr = __ldg(gxp + jg_g);
    float xz = __ldg(gxp + HID + jg_g);
    float xn = __ldg(gxp + 2 * HID + jg_g);

    for (int t = 0; t < T_STEPS; t++) {
        const float* hprev = (t == 0) ? h0 : out + (size_t)(t - 1) * BATCH * HID;

        // early: fp32 h_prev for the blend (single scalar per thread, L2 hit)
        float hpv = __ldg(hprev + (size_t)bg_g * HID + jg_g);

        // stage h tile as fp16 (16 x 512), coalesced loads, STS.64
#pragma unroll
        for (int q = 0; q < 8; q++) {
            int f = q * 256 + tid;
            int rr = f >> 7;
            int c4 = f & 127;
            float4 v = *((const float4*)(hprev + (size_t)(b0 + rr) * HID) + c4);
            uint2 u = make_uint2(pack_h2(v.x, v.y), pack_h2(v.z, v.w));
            *(uint2*)&h_sh[rr * HSH_PITCH + c4 * 4] = u;
        }
        __syncthreads();

        // MMA over this warp's k-slice: 4 k16-steps x 6 n-tiles
        float acc[6][4];
#pragma unroll
        for (int tl = 0; tl < 6; tl++) {
            acc[tl][0] = 0.f; acc[tl][1] = 0.f; acc[tl][2] = 0.f; acc[tl][3] = 0.f;
        }
#pragma unroll
        for (int kk = 0; kk < 4; kk++) {
            int kbase = (w * 4 + kk) * 16;
            uint32_t a0 = *(const uint32_t*)&h_sh[frow * HSH_PITCH + kbase + fk * 2];
            uint32_t a1 = *(const uint32_t*)&h_sh[(frow + 8) * HSH_PITCH + kbase + fk * 2];
            uint32_t a2 = *(const uint32_t*)&h_sh[frow * HSH_PITCH + kbase + 8 + fk * 2];
            uint32_t a3 = *(const uint32_t*)&h_sh[(frow + 8) * HSH_PITCH + kbase + 8 + fk * 2];
#pragma unroll
            for (int tl = 0; tl < 6; tl++)
                MMA_F16(acc[tl], a0, a1, a2, a3, wb0[tl][kk], wb1[tl][kk]);
        }
        {
            int m = lane >> 2;
            int ncb = 2 * (lane & 3);
#pragma unroll
            for (int tl = 0; tl < 6; tl++) {
                *(float2*)&Ps[(w * 16 + m) * PS_PITCH + tl * 8 + ncb] =
                    make_float2(acc[tl][0], acc[tl][1]);
                *(float2*)&Ps[(w * 16 + m + 8) * PS_PITCH + tl * 8 + ncb] =
                    make_float2(acc[tl][2], acc[tl][3]);
            }
        }
        __syncthreads();

        // reduce 8 partials + gating
        float hr = 0.f, hz = 0.f, hn = 0.f;
#pragma unroll
        for (int ww = 0; ww < 8; ww++) {
            const float* p = &Ps[(ww * 16 + gb) * PS_PITCH];
            hr += p[gj];
            hz += p[16 + gj];
            hn += p[32 + gj];
        }
        float r = 1.0f / (1.0f + __expf(-(xr + hr + br_)));
        float z = 1.0f / (1.0f + __expf(-(xz + hz + bz_)));
        float n = tanhf(xn + r * (hn + bn_));

        out[(size_t)t * BATCH * HID + (size_t)bg_g * HID + jg_g] =
            (1.0f - z) * n + z * hpv;

        // prefetch next step's input-side gates (hides L2 behind barrier wait)
        int tn = (t + 1 < T_STEPS) ? t + 1 : t;
        const float* gxn = gx_all + (size_t)tn * BATCH * GATES + (size_t)bg_g * GATES;
        xr = __ldg(gxn + jg_g);
        xz = __ldg(gxn + HID + jg_g);
        xn = __ldg(gxn + 2 * HID + jg_g);

        if (t != T_STEPS - 1)
            group_barrier(bt, 32);
    }
}

// ---------------------------------------------------------------------------
extern "C" void kernel_launch(void* const* d_in, const int* in_sizes, int n_in,
                              void* d_out, int out_size)
{
    const float* x    = (const float*)d_in[0];
    const float* h0   = (const float*)d_in[1];
    const float* w_ih = (const float*)d_in[2];
    const float* w_hh = (const float*)d_in[3];
    const float* b_ih = (const float*)d_in[4];
    const float* b_hh = (const float*)d_in[5];
    float* out_final  = (float*)d_out;

    float* gates; float* buf1; uint32_t* wfrag;
    cudaGetSymbolAddress((void**)&gates, g_gates);
    cudaGetSymbolAddress((void**)&buf1, g_buf1);
    cudaGetSymbolAddress((void**)&wfrag, g_wfrag);

    static int smem_configured = 0;
    if (!smem_configured) {
        cudaFuncSetAttribute(gru_layer_mma,
                             cudaFuncAttributeMaxDynamicSharedMemorySize, REC_SMEM_BYTES);
        smem_configured = 1;
    }

    const int M = T_STEPS * BATCH;
    const int K = HID;

    for (int l = 0; l < NLAYERS; l++) {
        const float* inp   = (l == 0) ? x : buf1;
        float*       out   = (l == NLAYERS - 1) ? out_final : buf1;
        const float* wih_l = w_ih + (size_t)l * GATES * HID;
        const float* whh_l = w_hh + (size_t)l * GATES * HID;
        const float* bih_l = b_ih + (size_t)l * GATES;
        const float* bhh_l = b_hh + (size_t)l * GATES;
        const float* h0_l  = h0 + (size_t)l * BATCH * HID;

        conv_wfrag_h<<<1536, 256>>>(wih_l, wfrag);

        dim3 ggrid(GATES / 128, M / 64);
        gemm_f16<<<ggrid, 256>>>(inp, wfrag, bih_l, gates, M, GATES, K);

        gru_layer_mma<<<128, 256, REC_SMEM_BYTES>>>(gates, h0_l, whh_l, bhh_l, out);
    }
}